// round 1
// baseline (speedup 1.0000x reference)
#include <cuda_runtime.h>

#define CC    512
#define TT    16
#define PP    576          // H*W
#define NN    9216         // T*P
#define CN    4718592      // C*NN (per batch)
#define NHEAD 8
#define DHEAD 64
#define TOTAL 9437184      // 2*CN

// Scratch (device-global arrays: the allowed no-alloc workaround)
__device__ float g_q[TOTAL];     // [b][t][head][p][d]
__device__ float g_k[TOTAL];
__device__ float g_v[TOTAL];
__device__ float g_attn[TOTAL];  // [b][c][t*P+p]

// ---------------------------------------------------------------------------
// GEMM: Y[o, n'] = sum_c W[o,c] * X[c, n'] (+pos) + bias[o]
// MODE 0: QKV (z = b*3+proj), input x(+pos_emb), scatter-store to g_q/g_k/g_v
// MODE 1: out proj (z = b), input g_attn, dense store to d_out
// Block tile 128x128, BK=8, 256 threads, 8x8 per thread (split 4+4).
// ---------------------------------------------------------------------------
template <int MODE>
__global__ __launch_bounds__(256) void gemm_kernel(
    const float* __restrict__ xin, const float* __restrict__ pos,
    const float* __restrict__ w0, const float* __restrict__ w1,
    const float* __restrict__ w2,
    const float* __restrict__ b0, const float* __restrict__ b1,
    const float* __restrict__ b2,
    float* __restrict__ outp)
{
    __shared__ __align__(16) float As[8][132];   // [k][m], padded
    __shared__ __align__(16) float Bs[8][128];   // [k][n]

    const int tid = threadIdx.x;
    const int tx = tid & 15;
    const int ty = tid >> 4;

    int bb;
    const float *W, *bias, *X;
    float* OUT;
    if (MODE == 0) {
        bb = blockIdx.z / 3;
        const int pr = blockIdx.z % 3;
        W    = (pr == 0) ? w0 : (pr == 1) ? w1 : w2;
        bias = (pr == 0) ? b0 : (pr == 1) ? b1 : b2;
        X    = xin + (size_t)bb * CN;
        OUT  = (pr == 0) ? g_q : (pr == 1) ? g_k : g_v;
    } else {
        bb   = blockIdx.z;
        W    = w0;
        bias = b0;
        X    = g_attn + (size_t)bb * CN;
        OUT  = outp + (size_t)bb * CN;
    }

    const int m0 = blockIdx.y * 128;
    const int n0 = blockIdx.x * 128;

    // global load mapping
    const int a_row = tid >> 1;            // 0..127 (o)
    const int a_col = (tid & 1) * 4;       // 0 or 4 (k)
    const int b_row = tid >> 5;            // 0..7   (k)
    const int b_col = (tid & 31) * 4;      // 0..124 (n)

    const float* Aptr = W + (size_t)(m0 + a_row) * CC + a_col;
    const float* Bptr = X + (size_t)b_row * NN + n0 + b_col;
    const float* Pptr = nullptr;
    if (MODE == 0) {
        const int t_b = (n0 + b_col) / PP;   // whole float4 shares t (576 % 4 == 0)
        Pptr = pos + b_row * TT + t_b;
    }

    float acc[8][8];
#pragma unroll
    for (int i = 0; i < 8; ++i)
#pragma unroll
        for (int j = 0; j < 8; ++j) acc[i][j] = 0.f;

    float4 av = *(const float4*)Aptr;
    float4 bv = *(const float4*)Bptr;
    float pz = (MODE == 0) ? *Pptr : 0.f;

    for (int kt = 0; kt < 64; ++kt) {
        As[a_col + 0][a_row] = av.x;
        As[a_col + 1][a_row] = av.y;
        As[a_col + 2][a_row] = av.z;
        As[a_col + 3][a_row] = av.w;
        if (MODE == 0) { bv.x += pz; bv.y += pz; bv.z += pz; bv.w += pz; }
        *(float4*)&Bs[b_row][b_col] = bv;
        __syncthreads();
        if (kt < 63) {
            av = *(const float4*)(Aptr + (kt + 1) * 8);
            bv = *(const float4*)(Bptr + (size_t)(kt + 1) * 8 * NN);
            if (MODE == 0) pz = Pptr[(kt + 1) * 8 * TT];
        }
#pragma unroll
        for (int k = 0; k < 8; ++k) {
            float4 a0 = *(const float4*)&As[k][ty * 4];
            float4 a1 = *(const float4*)&As[k][64 + ty * 4];
            float4 c0 = *(const float4*)&Bs[k][tx * 4];
            float4 c1 = *(const float4*)&Bs[k][64 + tx * 4];
            float ar[8] = {a0.x, a0.y, a0.z, a0.w, a1.x, a1.y, a1.z, a1.w};
            float br[8] = {c0.x, c0.y, c0.z, c0.w, c1.x, c1.y, c1.z, c1.w};
#pragma unroll
            for (int i = 0; i < 8; ++i)
#pragma unroll
                for (int j = 0; j < 8; ++j)
                    acc[i][j] = fmaf(ar[i], br[j], acc[i][j]);
        }
        __syncthreads();
    }

    if (MODE == 0) {
        // rows m0+g*64+ty*4+i -> head = m0/64+g, d = ty*4+i
#pragma unroll
        for (int g = 0; g < 2; ++g) {
            const int head = (m0 >> 6) + g;
            const int d0 = ty * 4;
            float4 b4;
            b4.x = bias[m0 + g * 64 + d0 + 0];
            b4.y = bias[m0 + g * 64 + d0 + 1];
            b4.z = bias[m0 + g * 64 + d0 + 2];
            b4.w = bias[m0 + g * 64 + d0 + 3];
#pragma unroll
            for (int j = 0; j < 8; ++j) {
                const int np = n0 + ((j < 4) ? (tx * 4 + j) : (64 + tx * 4 + j - 4));
                const int tt = np / PP;
                const int pp2 = np - tt * PP;
                float4 v;
                v.x = acc[g * 4 + 0][j] + b4.x;
                v.y = acc[g * 4 + 1][j] + b4.y;
                v.z = acc[g * 4 + 2][j] + b4.z;
                v.w = acc[g * 4 + 3][j] + b4.w;
                float* dst = OUT +
                    (((size_t)((bb * TT + tt) * NHEAD + head) * PP + pp2) << 6) + d0;
                *(float4*)dst = v;
            }
        }
    } else {
#pragma unroll
        for (int i = 0; i < 8; ++i) {
            const int m = m0 + ((i < 4) ? (ty * 4 + i) : (64 + ty * 4 + i - 4));
            const float bbv = bias[m];
            float4 v0 = {acc[i][0] + bbv, acc[i][1] + bbv, acc[i][2] + bbv, acc[i][3] + bbv};
            float4 v1 = {acc[i][4] + bbv, acc[i][5] + bbv, acc[i][6] + bbv, acc[i][7] + bbv};
            float* dst = OUT + (size_t)m * NN + n0 + tx * 4;
            *(float4*)dst = v0;
            *(float4*)(dst + 64) = v1;
        }
    }
}

// ---------------------------------------------------------------------------
// Flash attention per (b, head, t): P=576 keys, d=64. Block = one 64-row
// q-tile, loops 9 k-tiles of 64. 256 threads as 16x16, 4x4 S / 4x4 O each.
// Row groups live inside 16-lane halves -> width-16 shfl reductions.
// ---------------------------------------------------------------------------
__global__ __launch_bounds__(256) void attn_kernel()
{
    extern __shared__ __align__(16) float sm[];
    float* Qt = sm;                 // [64][68] Qt[d][p]
    float* Kt = sm + 64 * 68;       // [64][68] Kt[d][q]
    float* Vs = sm + 2 * 64 * 68;   // [64][68] Vs[q][d]
    float* Ps = sm + 3 * 64 * 68;   // [64][68] Ps[p][q], reused as Ot[d][p]

    const int tid = threadIdx.x;
    const int tx = tid & 15;
    const int ty = tid >> 4;

    const int bnt = blockIdx.y;
    const int qt = blockIdx.x;
    const int b = bnt >> 7;
    const int n = (bnt >> 4) & 7;
    const int t = bnt & 15;

    const size_t base = (size_t)((b * TT + t) * NHEAD + n) * PP * DHEAD;
    const float* Qg = g_q + base + (size_t)qt * 64 * DHEAD;
    const float* Kg = g_k + base;
    const float* Vg = g_v + base;

    // load Q transposed (once per block)
#pragma unroll
    for (int it = 0; it < 4; ++it) {
        const int f = tid + it * 256;
        const int row = f >> 4;          // p
        const int c4 = (f & 15) << 2;    // d
        float4 v = *(const float4*)(Qg + row * 64 + c4);
        Qt[(c4 + 0) * 68 + row] = v.x;
        Qt[(c4 + 1) * 68 + row] = v.y;
        Qt[(c4 + 2) * 68 + row] = v.z;
        Qt[(c4 + 3) * 68 + row] = v.w;
    }

    float m_i[4], l_i[4], o_acc[4][4];
#pragma unroll
    for (int i = 0; i < 4; ++i) {
        m_i[i] = -1e30f;
        l_i[i] = 0.f;
#pragma unroll
        for (int j = 0; j < 4; ++j) o_acc[i][j] = 0.f;
    }
    const float scale = 0.125f;   // 64^-0.5

    for (int kb = 0; kb < 9; ++kb) {
        __syncthreads();   // Qt ready / previous tile's reads done
#pragma unroll
        for (int it = 0; it < 4; ++it) {
            const int f = tid + it * 256;
            const int row = f >> 4;
            const int c4 = (f & 15) << 2;
            float4 kv = *(const float4*)(Kg + (size_t)(kb * 64 + row) * 64 + c4);
            Kt[(c4 + 0) * 68 + row] = kv.x;
            Kt[(c4 + 1) * 68 + row] = kv.y;
            Kt[(c4 + 2) * 68 + row] = kv.z;
            Kt[(c4 + 3) * 68 + row] = kv.w;
            *(float4*)&Vs[row * 68 + c4] =
                *(const float4*)(Vg + (size_t)(kb * 64 + row) * 64 + c4);
        }
        __syncthreads();

        // S = Q K^T (raw, scale folded into exp)
        float s[4][4];
#pragma unroll
        for (int i = 0; i < 4; ++i)
#pragma unroll
            for (int j = 0; j < 4; ++j) s[i][j] = 0.f;
#pragma unroll 16
        for (int d = 0; d < 64; ++d) {
            float4 q = *(const float4*)&Qt[d * 68 + ty * 4];
            float4 k = *(const float4*)&Kt[d * 68 + tx * 4];
            float qa[4] = {q.x, q.y, q.z, q.w};
            float ka[4] = {k.x, k.y, k.z, k.w};
#pragma unroll
            for (int i = 0; i < 4; ++i)
#pragma unroll
                for (int j = 0; j < 4; ++j)
                    s[i][j] = fmaf(qa[i], ka[j], s[i][j]);
        }

        // online softmax update + P store (row-major -> conflict-free STS)
#pragma unroll
        for (int i = 0; i < 4; ++i) {
            float mx = fmaxf(fmaxf(s[i][0], s[i][1]), fmaxf(s[i][2], s[i][3]));
#pragma unroll
            for (int off = 8; off > 0; off >>= 1)
                mx = fmaxf(mx, __shfl_xor_sync(0xffffffffu, mx, off));
            const float mnew = fmaxf(m_i[i], mx);
            const float alpha = __expf((m_i[i] - mnew) * scale);
            const float p0 = __expf((s[i][0] - mnew) * scale);
            const float p1 = __expf((s[i][1] - mnew) * scale);
            const float p2 = __expf((s[i][2] - mnew) * scale);
            const float p3 = __expf((s[i][3] - mnew) * scale);
            float rs = p0 + p1 + p2 + p3;
#pragma unroll
            for (int off = 8; off > 0; off >>= 1)
                rs += __shfl_xor_sync(0xffffffffu, rs, off);
            l_i[i] = l_i[i] * alpha + rs;
            m_i[i] = mnew;
#pragma unroll
            for (int j = 0; j < 4; ++j) o_acc[i][j] *= alpha;
            *(float4*)&Ps[(ty * 4 + i) * 68 + tx * 4] = make_float4(p0, p1, p2, p3);
        }
        __syncthreads();

        // O += P V  (P rows broadcast, V float4 rows)
#pragma unroll 8
        for (int q = 0; q < 64; ++q) {
            float4 vv = *(const float4*)&Vs[q * 68 + tx * 4];
            const float pb0 = Ps[(ty * 4 + 0) * 68 + q];
            const float pb1 = Ps[(ty * 4 + 1) * 68 + q];
            const float pb2 = Ps[(ty * 4 + 2) * 68 + q];
            const float pb3 = Ps[(ty * 4 + 3) * 68 + q];
            o_acc[0][0] = fmaf(pb0, vv.x, o_acc[0][0]);
            o_acc[0][1] = fmaf(pb0, vv.y, o_acc[0][1]);
            o_acc[0][2] = fmaf(pb0, vv.z, o_acc[0][2]);
            o_acc[0][3] = fmaf(pb0, vv.w, o_acc[0][3]);
            o_acc[1][0] = fmaf(pb1, vv.x, o_acc[1][0]);
            o_acc[1][1] = fmaf(pb1, vv.y, o_acc[1][1]);
            o_acc[1][2] = fmaf(pb1, vv.z, o_acc[1][2]);
            o_acc[1][3] = fmaf(pb1, vv.w, o_acc[1][3]);
            o_acc[2][0] = fmaf(pb2, vv.x, o_acc[2][0]);
            o_acc[2][1] = fmaf(pb2, vv.y, o_acc[2][1]);
            o_acc[2][2] = fmaf(pb2, vv.z, o_acc[2][2]);
            o_acc[2][3] = fmaf(pb2, vv.w, o_acc[2][3]);
            o_acc[3][0] = fmaf(pb3, vv.x, o_acc[3][0]);
            o_acc[3][1] = fmaf(pb3, vv.y, o_acc[3][1]);
            o_acc[3][2] = fmaf(pb3, vv.z, o_acc[3][2]);
            o_acc[3][3] = fmaf(pb3, vv.w, o_acc[3][3]);
        }
    }

    __syncthreads();
    // normalize + transpose to Ot[d][p] (reuse Ps), then coalesced store
#pragma unroll
    for (int i = 0; i < 4; ++i) {
        const float inv = 1.f / l_i[i];
#pragma unroll
        for (int j = 0; j < 4; ++j)
            Ps[(tx * 4 + j) * 68 + (ty * 4 + i)] = o_acc[i][j] * inv;
    }
    __syncthreads();

    float* goA = g_attn + (size_t)b * CN + (size_t)t * PP + qt * 64;
#pragma unroll
    for (int it = 0; it < 4; ++it) {
        const int f = tid + it * 256;
        const int d = f >> 4;
        const int p4 = (f & 15) << 2;
        float4 v = *(const float4*)&Ps[d * 68 + p4];
        *(float4*)(goA + (size_t)(n * 64 + d) * NN + p4) = v;
    }
}

// ---------------------------------------------------------------------------
extern "C" void kernel_launch(void* const* d_in, const int* in_sizes, int n_in,
                              void* d_out, int out_size)
{
    const float* x   = (const float*)d_in[0];
    const float* wq  = (const float*)d_in[1];
    const float* bq  = (const float*)d_in[2];
    const float* wk  = (const float*)d_in[3];
    const float* bk  = (const float*)d_in[4];
    const float* wv  = (const float*)d_in[5];
    const float* bv  = (const float*)d_in[6];
    const float* wo  = (const float*)d_in[7];
    const float* bo  = (const float*)d_in[8];
    const float* pos = (const float*)d_in[9];

    (void)in_sizes; (void)n_in; (void)out_size;

    // QKV projections (+pos_emb), scatter to [b][t][head][p][d]
    gemm_kernel<0><<<dim3(72, 4, 6), 256>>>(x, pos, wq, wk, wv, bq, bk, bv, nullptr);

    // attention
    const size_t shm = 4 * 64 * 68 * sizeof(float);   // 69632 B
    cudaFuncSetAttribute(attn_kernel, cudaFuncAttributeMaxDynamicSharedMemorySize,
                         (int)shm);
    attn_kernel<<<dim3(9, 256), 256, shm>>>();

    // output projection -> d_out ([B,C,T,H,W])
    gemm_kernel<1><<<dim3(72, 4, 2), 256>>>(nullptr, nullptr, wo, nullptr, nullptr,
                                            bo, nullptr, nullptr, (float*)d_out);
}

// round 4
// speedup vs baseline: 1.3701x; 1.3701x over previous
#include <cuda_runtime.h>
#include <cstdint>

#define CC    512
#define TT    16
#define PP    576
#define NN    9216
#define CN    4718592
#define NHEAD 8
#define TOTAL 9437184

#define STR   36                   // padded floats per SMEM row (bank-safe)
#define SSZ   (2*128*STR)          // floats per stage (A tile + B tile)

__device__ float g_xt[TOTAL];      // [tok][c]  (x + pos, tf32-rounded)
__device__ float g_q[TOTAL];       // token-major [b][t][p][512]
__device__ float g_k[TOTAL];
__device__ float g_v[TOTAL];
__device__ float g_attn[TOTAL];    // [tok][c]  (tf32-rounded)
__device__ float g_wr[4*CC*CC];    // tf32-rounded wq,wk,wv,wo

__device__ __forceinline__ float to_tf32(float x){
    float r; asm("cvt.rna.tf32.f32 %0, %1;" : "=f"(r) : "f"(x)); return r;
}

__device__ __forceinline__ void mma8(float4& d,
    uint32_t a0, uint32_t a1, uint32_t a2, uint32_t a3,
    uint32_t b0, uint32_t b1)
{
    asm volatile(
        "mma.sync.aligned.m16n8k8.row.col.f32.tf32.tf32.f32 "
        "{%0,%1,%2,%3}, {%4,%5,%6,%7}, {%8,%9}, {%0,%1,%2,%3};"
        : "+f"(d.x), "+f"(d.y), "+f"(d.z), "+f"(d.w)
        : "r"(a0), "r"(a1), "r"(a2), "r"(a3), "r"(b0), "r"(b1));
}

// ---------------------------------------------------------------------------
// prep: round weights to tf32 into g_wr
// ---------------------------------------------------------------------------
__global__ void prep_w(const float* __restrict__ wq, const float* __restrict__ wk,
                       const float* __restrict__ wv, const float* __restrict__ wo){
    int i = blockIdx.x * 256 + threadIdx.x;
    g_wr[i]          = to_tf32(wq[i]);
    g_wr[262144 + i] = to_tf32(wk[i]);
    g_wr[524288 + i] = to_tf32(wv[i]);
    g_wr[786432 + i] = to_tf32(wo[i]);
}

// ---------------------------------------------------------------------------
// transpose x[b][c][n] + pos[c][t] -> g_xt[b*9216+n][c]  (tf32-rounded)
// ---------------------------------------------------------------------------
__global__ __launch_bounds__(256) void transpose_pos(
    const float* __restrict__ x, const float* __restrict__ pos){
    __shared__ float tile[32][33];
    const int n0 = blockIdx.x * 32, c0 = blockIdx.y * 32, b = blockIdx.z;
    const int tx = threadIdx.x & 31, ty = threadIdx.x >> 5;
    const int t = n0 / PP;   // 576 % 32 == 0 -> tile within one t
#pragma unroll
    for (int i = 0; i < 4; ++i){
        const int c = c0 + ty + i * 8;
        tile[ty + i * 8][tx] =
            to_tf32(x[((size_t)b * CC + c) * NN + n0 + tx] + pos[c * TT + t]);
    }
    __syncthreads();
#pragma unroll
    for (int i = 0; i < 4; ++i){
        const int n = n0 + ty + i * 8;
        g_xt[((size_t)b * NN + n) * CC + c0 + tx] = tile[tx][ty + i * 8];
    }
}

// ---------------------------------------------------------------------------
// mma.sync tf32 GEMM: D[128 tok, 128 out] = A[tok][c] * W[out][c]^T + bias
// MODE 0: A=g_xt, W per blockIdx.z (q/k/v), token-major store to g_q/g_k/g_v
// MODE 1: A=g_attn, W=wo, channel-major store to d_out
// 256 thr = 8 warps (2m x 4n), warp tile 64x32, BK=32, double-buffered SMEM.
// SMEM layout: permuted k -> pos (k%4)*8 + k/4, row stride 36 floats
//   => fragment loads are conflict-free LDS.128.
// ---------------------------------------------------------------------------
template<int MODE>
__global__ __launch_bounds__(256) void gemm_mma(
    const float* __restrict__ bi0, const float* __restrict__ bi1,
    const float* __restrict__ bi2, float* __restrict__ o_out)
{
    extern __shared__ float sm[];

    const int tid = threadIdx.x;
    const int m0 = blockIdx.x * 128;
    const int n0 = blockIdx.y * 128;

    const float* A;
    const float* Bw;
    const float* bias;
    float* OUT;
    if (MODE == 0){
        const int pr = blockIdx.z;
        A    = g_xt + (size_t)m0 * CC;
        Bw   = g_wr + (size_t)pr * 262144 + (size_t)n0 * CC;
        bias = (pr == 0) ? bi0 : (pr == 1) ? bi1 : bi2;
        OUT  = (pr == 0) ? g_q : (pr == 1) ? g_k : g_v;
    } else {
        A    = g_attn + (size_t)m0 * CC;
        Bw   = g_wr + 786432 + (size_t)n0 * CC;
        bias = bi0;
        OUT  = o_out;
    }

    const int row_l = tid >> 3;          // 0..31 (loader row, +32p)
    const int jl    = tid & 7;           // k-group
    const int wid = tid >> 5, lane = tid & 31;
    const int wm = wid >> 2, wn = wid & 3;
    const int r = lane >> 2, c = lane & 3;

    float4 pa[4], pb[4];

    auto ldg_tile = [&](int kt){
#pragma unroll
        for (int p = 0; p < 4; ++p){
            pa[p] = *(const float4*)(A  + (size_t)(row_l + p * 32) * CC + kt * 32 + jl * 4);
            pb[p] = *(const float4*)(Bw + (size_t)(row_l + p * 32) * CC + kt * 32 + jl * 4);
        }
    };
    auto sts_tile = [&](int buf){
        float* As = sm + buf * SSZ;
        float* Bs = As + 128 * STR;
#pragma unroll
        for (int p = 0; p < 4; ++p){
            const int ro = (row_l + p * 32) * STR;
            As[ro + 0 * 8 + jl] = pa[p].x;
            As[ro + 1 * 8 + jl] = pa[p].y;
            As[ro + 2 * 8 + jl] = pa[p].z;
            As[ro + 3 * 8 + jl] = pa[p].w;
            Bs[ro + 0 * 8 + jl] = pb[p].x;
            Bs[ro + 1 * 8 + jl] = pb[p].y;
            Bs[ro + 2 * 8 + jl] = pb[p].z;
            Bs[ro + 3 * 8 + jl] = pb[p].w;
        }
    };

    float4 acc[4][4];
#pragma unroll
    for (int i = 0; i < 4; ++i)
#pragma unroll
        for (int j = 0; j < 4; ++j) acc[i][j] = make_float4(0.f, 0.f, 0.f, 0.f);

    ldg_tile(0);
    sts_tile(0);
    __syncthreads();
    ldg_tile(1);

    for (int kt = 0; kt < 16; ++kt){
        const int buf = kt & 1;
        const float* As = sm + buf * SSZ;
        const float* Bs = As + 128 * STR;
#pragma unroll
        for (int kp = 0; kp < 2; ++kp){
            float4 alo[4], ahi[4], bf[4];
#pragma unroll
            for (int mi = 0; mi < 4; ++mi){
                const int br = wm * 64 + mi * 16 + r;
                alo[mi] = *(const float4*)&As[br * STR + c * 8 + kp * 4];
                ahi[mi] = *(const float4*)&As[(br + 8) * STR + c * 8 + kp * 4];
            }
#pragma unroll
            for (int ni = 0; ni < 4; ++ni){
                const int bn = wn * 32 + ni * 8 + r;
                bf[ni] = *(const float4*)&Bs[bn * STR + c * 8 + kp * 4];
            }
#pragma unroll
            for (int mi = 0; mi < 4; ++mi)
#pragma unroll
                for (int ni = 0; ni < 4; ++ni){
                    mma8(acc[mi][ni],
                         __float_as_uint(alo[mi].x), __float_as_uint(ahi[mi].x),
                         __float_as_uint(alo[mi].y), __float_as_uint(ahi[mi].y),
                         __float_as_uint(bf[ni].x),  __float_as_uint(bf[ni].y));
                    mma8(acc[mi][ni],
                         __float_as_uint(alo[mi].z), __float_as_uint(ahi[mi].z),
                         __float_as_uint(alo[mi].w), __float_as_uint(ahi[mi].w),
                         __float_as_uint(bf[ni].z),  __float_as_uint(bf[ni].w));
                }
        }
        __syncthreads();
        if (kt < 15){
            sts_tile(buf ^ 1);
            __syncthreads();
            if (kt < 14) ldg_tile(kt + 2);
        }
    }

    // epilogue: direct fragment store (+bias)
    if (MODE == 0){
#pragma unroll
        for (int mi = 0; mi < 4; ++mi){
            const int row = m0 + wm * 64 + mi * 16 + r;
#pragma unroll
            for (int ni = 0; ni < 4; ++ni){
                const int col = n0 + wn * 32 + ni * 8 + 2 * c;
                const float b0 = __ldg(bias + col), b1 = __ldg(bias + col + 1);
                float* o0 = OUT + (size_t)row * CC + col;
                float2 v0 = {acc[mi][ni].x + b0, acc[mi][ni].y + b1};
                float2 v1 = {acc[mi][ni].z + b0, acc[mi][ni].w + b1};
                *(float2*)o0 = v0;
                *(float2*)(o0 + (size_t)8 * CC) = v1;
            }
        }
    } else {
        const int b = (m0 >= NN) ? 1 : 0;
        const int tbase = m0 - b * NN;
#pragma unroll
        for (int mi = 0; mi < 4; ++mi){
            const int ltok = wm * 64 + mi * 16 + r;
            float* ob = OUT + (size_t)b * CN + tbase + ltok;
#pragma unroll
            for (int ni = 0; ni < 4; ++ni){
                const int col = n0 + wn * 32 + ni * 8 + 2 * c;
                const float b0 = __ldg(bias + col), b1 = __ldg(bias + col + 1);
                ob[(size_t)col * NN]           = acc[mi][ni].x + b0;
                ob[(size_t)(col + 1) * NN]     = acc[mi][ni].y + b1;
                ob[(size_t)col * NN + 8]       = acc[mi][ni].z + b0;
                ob[(size_t)(col + 1) * NN + 8] = acc[mi][ni].w + b1;
            }
        }
    }
}

// ---------------------------------------------------------------------------
// Flash attention per (b, head, t): P=576, d=64, token-major Q/K/V rows.
// ---------------------------------------------------------------------------
__global__ __launch_bounds__(256) void attn_kernel()
{
    extern __shared__ __align__(16) float sm[];
    float* Qt = sm;                 // [64][68] Qt[d][p]
    float* Kt = sm + 64 * 68;       // [64][68] Kt[d][q]
    float* Vs = sm + 2 * 64 * 68;   // [64][68] Vs[q][d]
    float* Ps = sm + 3 * 64 * 68;   // [64][68] Ps[p][q]

    const int tid = threadIdx.x;
    const int tx = tid & 15;
    const int ty = tid >> 4;

    const int bnt = blockIdx.y;
    const int qt = blockIdx.x;
    const int b = bnt >> 7;
    const int n = (bnt >> 4) & 7;
    const int t = bnt & 15;

    const size_t base = (size_t)((b * TT + t) * PP) * CC;
    const int col0 = n * 64;
    const float* Qg = g_q + base + (size_t)qt * 64 * CC + col0;
    const float* Kg = g_k + base + col0;
    const float* Vg = g_v + base + col0;

#pragma unroll
    for (int it = 0; it < 4; ++it){
        const int f = tid + it * 256;
        const int row = f >> 4;
        const int c4 = (f & 15) << 2;
        float4 v = *(const float4*)(Qg + (size_t)row * CC + c4);
        Qt[(c4 + 0) * 68 + row] = v.x;
        Qt[(c4 + 1) * 68 + row] = v.y;
        Qt[(c4 + 2) * 68 + row] = v.z;
        Qt[(c4 + 3) * 68 + row] = v.w;
    }

    float m_i[4], l_i[4], o_acc[4][4];
#pragma unroll
    for (int i = 0; i < 4; ++i){
        m_i[i] = -1e30f; l_i[i] = 0.f;
#pragma unroll
        for (int j = 0; j < 4; ++j) o_acc[i][j] = 0.f;
    }
    const float scale = 0.125f;

    for (int kb = 0; kb < 9; ++kb){
        __syncthreads();
#pragma unroll
        for (int it = 0; it < 4; ++it){
            const int f = tid + it * 256;
            const int row = f >> 4;
            const int c4 = (f & 15) << 2;
            float4 kv = *(const float4*)(Kg + (size_t)(kb * 64 + row) * CC + c4);
            Kt[(c4 + 0) * 68 + row] = kv.x;
            Kt[(c4 + 1) * 68 + row] = kv.y;
            Kt[(c4 + 2) * 68 + row] = kv.z;
            Kt[(c4 + 3) * 68 + row] = kv.w;
            *(float4*)&Vs[row * 68 + c4] =
                *(const float4*)(Vg + (size_t)(kb * 64 + row) * CC + c4);
        }
        __syncthreads();

        float s[4][4];
#pragma unroll
        for (int i = 0; i < 4; ++i)
#pragma unroll
            for (int j = 0; j < 4; ++j) s[i][j] = 0.f;
#pragma unroll 16
        for (int d = 0; d < 64; ++d){
            float4 q = *(const float4*)&Qt[d * 68 + ty * 4];
            float4 k = *(const float4*)&Kt[d * 68 + tx * 4];
            float qa[4] = {q.x, q.y, q.z, q.w};
            float ka[4] = {k.x, k.y, k.z, k.w};
#pragma unroll
            for (int i = 0; i < 4; ++i)
#pragma unroll
                for (int j = 0; j < 4; ++j)
                    s[i][j] = fmaf(qa[i], ka[j], s[i][j]);
        }

#pragma unroll
        for (int i = 0; i < 4; ++i){
            float mx = fmaxf(fmaxf(s[i][0], s[i][1]), fmaxf(s[i][2], s[i][3]));
#pragma unroll
            for (int off = 8; off > 0; off >>= 1)
                mx = fmaxf(mx, __shfl_xor_sync(0xffffffffu, mx, off));
            const float mnew = fmaxf(m_i[i], mx);
            const float alpha = __expf((m_i[i] - mnew) * scale);
            const float p0 = __expf((s[i][0] - mnew) * scale);
            const float p1 = __expf((s[i][1] - mnew) * scale);
            const float p2 = __expf((s[i][2] - mnew) * scale);
            const float p3 = __expf((s[i][3] - mnew) * scale);
            float rs = p0 + p1 + p2 + p3;
#pragma unroll
            for (int off = 8; off > 0; off >>= 1)
                rs += __shfl_xor_sync(0xffffffffu, rs, off);
            l_i[i] = l_i[i] * alpha + rs;
            m_i[i] = mnew;
#pragma unroll
            for (int j = 0; j < 4; ++j) o_acc[i][j] *= alpha;
            *(float4*)&Ps[(ty * 4 + i) * 68 + tx * 4] = make_float4(p0, p1, p2, p3);
        }
        __syncthreads();

#pragma unroll 8
        for (int q = 0; q < 64; ++q){
            float4 vv = *(const float4*)&Vs[q * 68 + tx * 4];
            const float pb0 = Ps[(ty * 4 + 0) * 68 + q];
            const float pb1 = Ps[(ty * 4 + 1) * 68 + q];
            const float pb2 = Ps[(ty * 4 + 2) * 68 + q];
            const float pb3 = Ps[(ty * 4 + 3) * 68 + q];
            o_acc[0][0] = fmaf(pb0, vv.x, o_acc[0][0]);
            o_acc[0][1] = fmaf(pb0, vv.y, o_acc[0][1]);
            o_acc[0][2] = fmaf(pb0, vv.z, o_acc[0][2]);
            o_acc[0][3] = fmaf(pb0, vv.w, o_acc[0][3]);
            o_acc[1][0] = fmaf(pb1, vv.x, o_acc[1][0]);
            o_acc[1][1] = fmaf(pb1, vv.y, o_acc[1][1]);
            o_acc[1][2] = fmaf(pb1, vv.z, o_acc[1][2]);
            o_acc[1][3] = fmaf(pb1, vv.w, o_acc[1][3]);
            o_acc[2][0] = fmaf(pb2, vv.x, o_acc[2][0]);
            o_acc[2][1] = fmaf(pb2, vv.y, o_acc[2][1]);
            o_acc[2][2] = fmaf(pb2, vv.z, o_acc[2][2]);
            o_acc[2][3] = fmaf(pb2, vv.w, o_acc[2][3]);
            o_acc[3][0] = fmaf(pb3, vv.x, o_acc[3][0]);
            o_acc[3][1] = fmaf(pb3, vv.y, o_acc[3][1]);
            o_acc[3][2] = fmaf(pb3, vv.z, o_acc[3][2]);
            o_acc[3][3] = fmaf(pb3, vv.w, o_acc[3][3]);
        }
    }

    // direct token-major store (tf32-rounded for the out-proj MMA)
    float* goA = g_attn + base + (size_t)qt * 64 * CC + col0;
#pragma unroll
    for (int i = 0; i < 4; ++i){
        const float inv = 1.f / l_i[i];
        float4 v;
        v.x = to_tf32(o_acc[i][0] * inv);
        v.y = to_tf32(o_acc[i][1] * inv);
        v.z = to_tf32(o_acc[i][2] * inv);
        v.w = to_tf32(o_acc[i][3] * inv);
        *(float4*)(goA + (size_t)(ty * 4 + i) * CC + tx * 4) = v;
    }
}

// ---------------------------------------------------------------------------
extern "C" void kernel_launch(void* const* d_in, const int* in_sizes, int n_in,
                              void* d_out, int out_size)
{
    const float* x   = (const float*)d_in[0];
    const float* wq  = (const float*)d_in[1];
    const float* bq  = (const float*)d_in[2];
    const float* wk  = (const float*)d_in[3];
    const float* bk  = (const float*)d_in[4];
    const float* wv  = (const float*)d_in[5];
    const float* bv  = (const float*)d_in[6];
    const float* wo  = (const float*)d_in[7];
    const float* bo  = (const float*)d_in[8];
    const float* pos = (const float*)d_in[9];
    (void)in_sizes; (void)n_in; (void)out_size;

    const int gemm_smem = 2 * SSZ * sizeof(float);   // 73728 B
    cudaFuncSetAttribute(gemm_mma<0>, cudaFuncAttributeMaxDynamicSharedMemorySize, gemm_smem);
    cudaFuncSetAttribute(gemm_mma<1>, cudaFuncAttributeMaxDynamicSharedMemorySize, gemm_smem);
    cudaFuncSetAttribute(attn_kernel, cudaFuncAttributeMaxDynamicSharedMemorySize,
                         (int)(4 * 64 * 68 * sizeof(float)));

    prep_w<<<1024, 256>>>(wq, wk, wv, wo);
    transpose_pos<<<dim3(288, 16, 2), 256>>>(x, pos);

    gemm_mma<0><<<dim3(144, 4, 3), 256, gemm_smem>>>(bq, bk, bv, nullptr);

    attn_kernel<<<dim3(9, 256), 256, 4 * 64 * 68 * sizeof(float)>>>();

    gemm_mma<1><<<dim3(144, 4), 256, gemm_smem>>>(bo, nullptr, nullptr, (float*)d_out);
}

// round 7
// speedup vs baseline: 2.3183x; 1.6920x over previous
#include <cuda_runtime.h>
#include <cstdint>

#define CC    512
#define TT    16
#define PP    576
#define NN    9216
#define CN    4718592
#define NHEAD 8
#define TOTAL 9437184

#define STR   36                   // GEMM: padded floats per SMEM row
#define SSZ   (2*128*STR)          // GEMM: floats per stage

// attention smem strides
#define KSTR  68                   // Kt / Ps stride (banks: 4g+c distinct)
#define VSTR  76                   // Vt stride (banks: 12c+g distinct)
#define ATT_SMEM ((2*64*KSTR + 64*VSTR) * 4)   // 54272 B

__device__ float g_xt[TOTAL];      // [tok][c]  (x + pos, tf32-rounded)
__device__ float g_q[TOTAL];       // token-major [b][t][p][512]
__device__ float g_k[TOTAL];
__device__ float g_v[TOTAL];
__device__ float g_attn[TOTAL];    // [tok][c]  (tf32-rounded)
__device__ float g_wr[4*CC*CC];    // tf32-rounded wq,wk,wv,wo

__device__ __forceinline__ float to_tf32(float x){
    float r; asm("cvt.rna.tf32.f32 %0, %1;" : "=f"(r) : "f"(x)); return r;
}

__device__ __forceinline__ void mma8(float4& d,
    uint32_t a0, uint32_t a1, uint32_t a2, uint32_t a3,
    uint32_t b0, uint32_t b1)
{
    asm volatile(
        "mma.sync.aligned.m16n8k8.row.col.f32.tf32.tf32.f32 "
        "{%0,%1,%2,%3}, {%4,%5,%6,%7}, {%8,%9}, {%0,%1,%2,%3};"
        : "+f"(d.x), "+f"(d.y), "+f"(d.z), "+f"(d.w)
        : "r"(a0), "r"(a1), "r"(a2), "r"(a3), "r"(b0), "r"(b1));
}

// ---------------------------------------------------------------------------
// prep: round weights to tf32 into g_wr
// ---------------------------------------------------------------------------
__global__ void prep_w(const float* __restrict__ wq, const float* __restrict__ wk,
                       const float* __restrict__ wv, const float* __restrict__ wo){
    int i = blockIdx.x * 256 + threadIdx.x;
    g_wr[i]          = to_tf32(wq[i]);
    g_wr[262144 + i] = to_tf32(wk[i]);
    g_wr[524288 + i] = to_tf32(wv[i]);
    g_wr[786432 + i] = to_tf32(wo[i]);
}

// ---------------------------------------------------------------------------
// transpose x[b][c][n] + pos[c][t] -> g_xt[b*9216+n][c]  (tf32-rounded)
// ---------------------------------------------------------------------------
__global__ __launch_bounds__(256) void transpose_pos(
    const float* __restrict__ x, const float* __restrict__ pos){
    __shared__ float tile[32][33];
    const int n0 = blockIdx.x * 32, c0 = blockIdx.y * 32, b = blockIdx.z;
    const int tx = threadIdx.x & 31, ty = threadIdx.x >> 5;
    const int t = n0 / PP;
#pragma unroll
    for (int i = 0; i < 4; ++i){
        const int c = c0 + ty + i * 8;
        tile[ty + i * 8][tx] =
            to_tf32(x[((size_t)b * CC + c) * NN + n0 + tx] + pos[c * TT + t]);
    }
    __syncthreads();
#pragma unroll
    for (int i = 0; i < 4; ++i){
        const int n = n0 + ty + i * 8;
        g_xt[((size_t)b * NN + n) * CC + c0 + tx] = tile[tx][ty + i * 8];
    }
}

// ---------------------------------------------------------------------------
// mma.sync tf32 GEMM (validated in round 4)
// ---------------------------------------------------------------------------
template<int MODE>
__global__ __launch_bounds__(256) void gemm_mma(
    const float* __restrict__ bi0, const float* __restrict__ bi1,
    const float* __restrict__ bi2, float* __restrict__ o_out)
{
    extern __shared__ float sm[];

    const int tid = threadIdx.x;
    const int m0 = blockIdx.x * 128;
    const int n0 = blockIdx.y * 128;

    const float* A;
    const float* Bw;
    const float* bias;
    float* OUT;
    if (MODE == 0){
        const int pr = blockIdx.z;
        A    = g_xt + (size_t)m0 * CC;
        Bw   = g_wr + (size_t)pr * 262144 + (size_t)n0 * CC;
        bias = (pr == 0) ? bi0 : (pr == 1) ? bi1 : bi2;
        OUT  = (pr == 0) ? g_q : (pr == 1) ? g_k : g_v;
    } else {
        A    = g_attn + (size_t)m0 * CC;
        Bw   = g_wr + 786432 + (size_t)n0 * CC;
        bias = bi0;
        OUT  = o_out;
    }

    const int row_l = tid >> 3;
    const int jl    = tid & 7;
    const int wid = tid >> 5, lane = tid & 31;
    const int wm = wid >> 2, wn = wid & 3;
    const int r = lane >> 2, c = lane & 3;

    float4 pa[4], pb[4];

    auto ldg_tile = [&](int kt){
#pragma unroll
        for (int p = 0; p < 4; ++p){
            pa[p] = *(const float4*)(A  + (size_t)(row_l + p * 32) * CC + kt * 32 + jl * 4);
            pb[p] = *(const float4*)(Bw + (size_t)(row_l + p * 32) * CC + kt * 32 + jl * 4);
        }
    };
    auto sts_tile = [&](int buf){
        float* As = sm + buf * SSZ;
        float* Bs = As + 128 * STR;
#pragma unroll
        for (int p = 0; p < 4; ++p){
            const int ro = (row_l + p * 32) * STR;
            As[ro + 0 * 8 + jl] = pa[p].x;
            As[ro + 1 * 8 + jl] = pa[p].y;
            As[ro + 2 * 8 + jl] = pa[p].z;
            As[ro + 3 * 8 + jl] = pa[p].w;
            Bs[ro + 0 * 8 + jl] = pb[p].x;
            Bs[ro + 1 * 8 + jl] = pb[p].y;
            Bs[ro + 2 * 8 + jl] = pb[p].z;
            Bs[ro + 3 * 8 + jl] = pb[p].w;
        }
    };

    float4 acc[4][4];
#pragma unroll
    for (int i = 0; i < 4; ++i)
#pragma unroll
        for (int j = 0; j < 4; ++j) acc[i][j] = make_float4(0.f, 0.f, 0.f, 0.f);

    ldg_tile(0);
    sts_tile(0);
    __syncthreads();
    ldg_tile(1);

    for (int kt = 0; kt < 16; ++kt){
        const int buf = kt & 1;
        const float* As = sm + buf * SSZ;
        const float* Bs = As + 128 * STR;
#pragma unroll
        for (int kp = 0; kp < 2; ++kp){
            float4 alo[4], ahi[4], bf[4];
#pragma unroll
            for (int mi = 0; mi < 4; ++mi){
                const int br = wm * 64 + mi * 16 + r;
                alo[mi] = *(const float4*)&As[br * STR + c * 8 + kp * 4];
                ahi[mi] = *(const float4*)&As[(br + 8) * STR + c * 8 + kp * 4];
            }
#pragma unroll
            for (int ni = 0; ni < 4; ++ni){
                const int bn = wn * 32 + ni * 8 + r;
                bf[ni] = *(const float4*)&Bs[bn * STR + c * 8 + kp * 4];
            }
#pragma unroll
            for (int mi = 0; mi < 4; ++mi)
#pragma unroll
                for (int ni = 0; ni < 4; ++ni){
                    mma8(acc[mi][ni],
                         __float_as_uint(alo[mi].x), __float_as_uint(ahi[mi].x),
                         __float_as_uint(alo[mi].y), __float_as_uint(ahi[mi].y),
                         __float_as_uint(bf[ni].x),  __float_as_uint(bf[ni].y));
                    mma8(acc[mi][ni],
                         __float_as_uint(alo[mi].z), __float_as_uint(ahi[mi].z),
                         __float_as_uint(alo[mi].w), __float_as_uint(ahi[mi].w),
                         __float_as_uint(bf[ni].z),  __float_as_uint(bf[ni].w));
                }
        }
        __syncthreads();
        if (kt < 15){
            sts_tile(buf ^ 1);
            __syncthreads();
            if (kt < 14) ldg_tile(kt + 2);
        }
    }

    if (MODE == 0){
#pragma unroll
        for (int mi = 0; mi < 4; ++mi){
            const int row = m0 + wm * 64 + mi * 16 + r;
#pragma unroll
            for (int ni = 0; ni < 4; ++ni){
                const int col = n0 + wn * 32 + ni * 8 + 2 * c;
                const float b0 = __ldg(bias + col), b1 = __ldg(bias + col + 1);
                float* o0 = OUT + (size_t)row * CC + col;
                float2 v0 = {acc[mi][ni].x + b0, acc[mi][ni].y + b1};
                float2 v1 = {acc[mi][ni].z + b0, acc[mi][ni].w + b1};
                *(float2*)o0 = v0;
                *(float2*)(o0 + (size_t)8 * CC) = v1;
            }
        }
    } else {
        const int b = (m0 >= NN) ? 1 : 0;
        const int tbase = m0 - b * NN;
#pragma unroll
        for (int mi = 0; mi < 4; ++mi){
            const int ltok = wm * 64 + mi * 16 + r;
            float* ob = OUT + (size_t)b * CN + tbase + ltok;
#pragma unroll
            for (int ni = 0; ni < 4; ++ni){
                const int col = n0 + wn * 32 + ni * 8 + 2 * c;
                const float b0 = __ldg(bias + col), b1 = __ldg(bias + col + 1);
                ob[(size_t)col * NN]           = acc[mi][ni].x + b0;
                ob[(size_t)(col + 1) * NN]     = acc[mi][ni].y + b1;
                ob[(size_t)col * NN + 8]       = acc[mi][ni].z + b0;
                ob[(size_t)(col + 1) * NN + 8] = acc[mi][ni].w + b1;
            }
        }
    }
}

// ---------------------------------------------------------------------------
// Tensor-core flash attention: block = (qt, b*h*t), 128 thr (4 warps).
// Warp tile = 16 q-rows x 64 keys; Q fragments register-resident.
// ---------------------------------------------------------------------------
__global__ __launch_bounds__(128) void attn_mma()
{
    extern __shared__ __align__(16) float sm[];
    float* Kt = sm;                        // [64][KSTR]
    float* Vt = sm + 64 * KSTR;            // [64][VSTR]
    float* Ps = sm + 64 * KSTR + 64 * VSTR;// [64][KSTR] (Q staging, then P)

    const int tid  = threadIdx.x;
    const int lane = tid & 31, wid = tid >> 5;
    const int g = lane >> 2, c = lane & 3;

    const int bnt = blockIdx.y, qt = blockIdx.x;
    const int b = bnt >> 7, n = (bnt >> 4) & 7, t = bnt & 15;
    const size_t base = (size_t)((b * TT + t) * PP) * CC;
    const int col0 = n * 64;
    const float* Qg = g_q + base + (size_t)qt * 64 * CC + col0;
    const float* Kg = g_k + base + col0;
    const float* Vg = g_v + base + col0;

    // stage Q tile (64x64 = 1024 float4 slots, 128 thr -> 8 iters)
#pragma unroll
    for (int it = 0; it < 8; ++it){
        const int f = tid + it * 128;
        const int row = f >> 4, c4 = (f & 15) << 2;
        *(float4*)&Ps[row * KSTR + c4] = *(const float4*)(Qg + (size_t)row * CC + c4);
    }
    __syncthreads();

    // register-resident Q fragments (a-frags for all 8 k-steps)
    const int mrow = wid * 16 + g;
    uint32_t qf[8][4];
#pragma unroll
    for (int kk = 0; kk < 8; ++kk){
        qf[kk][0] = __float_as_uint(Ps[ mrow      * KSTR + kk * 8 + c    ]);
        qf[kk][1] = __float_as_uint(Ps[(mrow + 8) * KSTR + kk * 8 + c    ]);
        qf[kk][2] = __float_as_uint(Ps[ mrow      * KSTR + kk * 8 + c + 4]);
        qf[kk][3] = __float_as_uint(Ps[(mrow + 8) * KSTR + kk * 8 + c + 4]);
    }

    float m_i[2] = {-1e30f, -1e30f};
    float l_i[2] = {0.f, 0.f};
    float4 o[8];
#pragma unroll
    for (int i = 0; i < 8; ++i) o[i] = make_float4(0.f, 0.f, 0.f, 0.f);
    const float scale = 0.125f;

    for (int kb = 0; kb < 9; ++kb){
        __syncthreads();   // prior-tile Kt/Vt reads (and Q-stage reads) done
#pragma unroll
        for (int it = 0; it < 8; ++it){
            const int f = tid + it * 128;
            const int row = f >> 4, c4 = (f & 15) << 2;
            *(float4*)&Kt[row * KSTR + c4] =
                *(const float4*)(Kg + (size_t)(kb * 64 + row) * CC + c4);
            float4 vv = *(const float4*)(Vg + (size_t)(kb * 64 + row) * CC + c4);
            vv.x = to_tf32(vv.x); vv.y = to_tf32(vv.y);
            vv.z = to_tf32(vv.z); vv.w = to_tf32(vv.w);
            *(float4*)&Vt[row * VSTR + c4] = vv;
        }
        __syncthreads();

        // S = Q K^T : b0 = K[nf*8+g][kk*8+c], b1 = K[nf*8+g][kk*8+c+4]
        float4 s[8];
#pragma unroll
        for (int i = 0; i < 8; ++i) s[i] = make_float4(0.f, 0.f, 0.f, 0.f);
#pragma unroll
        for (int kk = 0; kk < 8; ++kk){
#pragma unroll
            for (int nf = 0; nf < 8; ++nf){
                const float* kr = &Kt[(nf * 8 + g) * KSTR + kk * 8 + c];
                mma8(s[nf], qf[kk][0], qf[kk][1], qf[kk][2], qf[kk][3],
                     __float_as_uint(kr[0]), __float_as_uint(kr[4]));
            }
        }

        // online softmax (rows mrow and mrow+8)
        float mx0 = -1e30f, mx1 = -1e30f;
#pragma unroll
        for (int nf = 0; nf < 8; ++nf){
            mx0 = fmaxf(mx0, fmaxf(s[nf].x, s[nf].y));
            mx1 = fmaxf(mx1, fmaxf(s[nf].z, s[nf].w));
        }
#pragma unroll
        for (int off = 1; off < 4; off <<= 1){
            mx0 = fmaxf(mx0, __shfl_xor_sync(0xffffffffu, mx0, off));
            mx1 = fmaxf(mx1, __shfl_xor_sync(0xffffffffu, mx1, off));
        }
        const float mn0 = fmaxf(m_i[0], mx0);
        const float mn1 = fmaxf(m_i[1], mx1);
        const float al0 = __expf((m_i[0] - mn0) * scale);
        const float al1 = __expf((m_i[1] - mn1) * scale);
        m_i[0] = mn0; m_i[1] = mn1;

        float rs0 = 0.f, rs1 = 0.f;
#pragma unroll
        for (int nf = 0; nf < 8; ++nf){
            float px = to_tf32(__expf((s[nf].x - mn0) * scale));
            float py = to_tf32(__expf((s[nf].y - mn0) * scale));
            float pz = to_tf32(__expf((s[nf].z - mn1) * scale));
            float pw = to_tf32(__expf((s[nf].w - mn1) * scale));
            rs0 += px + py; rs1 += pz + pw;
            *(float2*)&Ps[ mrow      * KSTR + nf * 8 + 2 * c] = make_float2(px, py);
            *(float2*)&Ps[(mrow + 8) * KSTR + nf * 8 + 2 * c] = make_float2(pz, pw);
        }
#pragma unroll
        for (int off = 1; off < 4; off <<= 1){
            rs0 += __shfl_xor_sync(0xffffffffu, rs0, off);
            rs1 += __shfl_xor_sync(0xffffffffu, rs1, off);
        }
        l_i[0] = l_i[0] * al0 + rs0;
        l_i[1] = l_i[1] * al1 + rs1;
#pragma unroll
        for (int nf = 0; nf < 8; ++nf){
            o[nf].x *= al0; o[nf].y *= al0;
            o[nf].z *= al1; o[nf].w *= al1;
        }
        __syncwarp();   // P visible to this warp's fragment loads

        // O += P V : a from Ps (own rows), b0 = V[kk*8+c][nf*8+g], b1 = +4 rows
#pragma unroll
        for (int kk = 0; kk < 8; ++kk){
            const uint32_t a0 = __float_as_uint(Ps[ mrow      * KSTR + kk * 8 + c    ]);
            const uint32_t a1 = __float_as_uint(Ps[(mrow + 8) * KSTR + kk * 8 + c    ]);
            const uint32_t a2 = __float_as_uint(Ps[ mrow      * KSTR + kk * 8 + c + 4]);
            const uint32_t a3 = __float_as_uint(Ps[(mrow + 8) * KSTR + kk * 8 + c + 4]);
#pragma unroll
            for (int nf = 0; nf < 8; ++nf){
                mma8(o[nf], a0, a1, a2, a3,
                     __float_as_uint(Vt[(kk * 8 + c    ) * VSTR + nf * 8 + g]),
                     __float_as_uint(Vt[(kk * 8 + c + 4) * VSTR + nf * 8 + g]));
            }
        }
        __syncwarp();   // P reads done before next tile overwrites Ps
    }

    // normalize + store token-major (tf32-rounded for out-proj)
    const float inv0 = 1.f / l_i[0];
    const float inv1 = 1.f / l_i[1];
    float* O0 = g_attn + base + (size_t)(qt * 64 + mrow) * CC + col0;
    float* O1 = O0 + (size_t)8 * CC;
#pragma unroll
    for (int nf = 0; nf < 8; ++nf){
        *(float2*)(O0 + nf * 8 + 2 * c) =
            make_float2(to_tf32(o[nf].x * inv0), to_tf32(o[nf].y * inv0));
        *(float2*)(O1 + nf * 8 + 2 * c) =
            make_float2(to_tf32(o[nf].z * inv1), to_tf32(o[nf].w * inv1));
    }
}

// ---------------------------------------------------------------------------
extern "C" void kernel_launch(void* const* d_in, const int* in_sizes, int n_in,
                              void* d_out, int out_size)
{
    const float* x   = (const float*)d_in[0];
    const float* wq  = (const float*)d_in[1];
    const float* bq  = (const float*)d_in[2];
    const float* wk  = (const float*)d_in[3];
    const float* bk  = (const float*)d_in[4];
    const float* wv  = (const float*)d_in[5];
    const float* bv  = (const float*)d_in[6];
    const float* wo  = (const float*)d_in[7];
    const float* bo  = (const float*)d_in[8];
    const float* pos = (const float*)d_in[9];
    (void)in_sizes; (void)n_in; (void)out_size;

    const int gemm_smem = 2 * SSZ * sizeof(float);
    cudaFuncSetAttribute(gemm_mma<0>, cudaFuncAttributeMaxDynamicSharedMemorySize, gemm_smem);
    cudaFuncSetAttribute(gemm_mma<1>, cudaFuncAttributeMaxDynamicSharedMemorySize, gemm_smem);
    cudaFuncSetAttribute(attn_mma, cudaFuncAttributeMaxDynamicSharedMemorySize, ATT_SMEM);

    prep_w<<<1024, 256>>>(wq, wk, wv, wo);
    transpose_pos<<<dim3(288, 16, 2), 256>>>(x, pos);

    gemm_mma<0><<<dim3(144, 4, 3), 256, gemm_smem>>>(bq, bk, bv, nullptr);

    attn_mma<<<dim3(9, 256), 128, ATT_SMEM>>>();

    gemm_mma<1><<<dim3(144, 4), 256, gemm_smem>>>(bo, nullptr, nullptr, (float*)d_out);
}